// round 13
// baseline (speedup 1.0000x reference)
#include <cuda_runtime.h>
#include <cstdint>

// PointConv: B=32, C=64, H=W=64, KH=KW=2 -> L=1024, n=256.
// Per l: D[p, b] = sum_k W[l][k][p] * patch[b][k] + bias[p, l]
// fp32 via 3-term bf16 split on mma.sync.m16n8k16.
// R13: split-p (2048 CTAs x 128 thr; CTA = l x p-half), warp-private W LDG
//      streams with .nc L1::no_allocate, B patch pre-formatted as mma
//      fragment stream (LDS.128 loads), no __syncthreads in mainloop.

#define HH 64
#define CC 64
#define NN 256
#define LL 1024

#define KSTAGE 16
#define NSTG   16

#define AWARP 4096                 // per-warp A buf: hi 2KB + mid 2KB
#define OFF_A    0                 // 4 warps x 4096 = 16384
#define OFF_P    16384             // frag stream: 16 s x 4 nt x 32 lanes x 16B = 32768
#define SMEM_TOTAL 49152

__device__ __forceinline__ uint32_t aswz(uint32_t r, uint32_t cb) {   // per-warp A tile
    return r * 128 + (cb ^ ((r & 7) << 4));
}
__device__ __forceinline__ uint32_t cvt2(float lo, float hi) {  // pack {lo=low16, hi=high16}
    uint32_t r;
    asm("cvt.rn.bf16x2.f32 %0, %1, %2;" : "=r"(r) : "f"(hi), "f"(lo));
    return r;
}
__device__ __forceinline__ float lo_f(uint32_t p) { return __uint_as_float(p << 16); }
__device__ __forceinline__ float hi_f(uint32_t p) { return __uint_as_float(p & 0xffff0000u); }

__device__ __forceinline__ float4 ldg_nc_v4(const float* p) {
    float4 v;
    asm("ld.global.nc.L1::no_allocate.v4.f32 {%0,%1,%2,%3}, [%4];"
        : "=f"(v.x), "=f"(v.y), "=f"(v.z), "=f"(v.w) : "l"(p));
    return v;
}
__device__ __forceinline__ float2 ldg_nc_v2(const float* p) {
    float2 v;
    asm("ld.global.nc.L1::no_allocate.v2.f32 {%0,%1}, [%2];"
        : "=f"(v.x), "=f"(v.y) : "l"(p));
    return v;
}
__device__ __forceinline__ void ldsm4t(uint32_t& r0, uint32_t& r1, uint32_t& r2, uint32_t& r3,
                                       uint32_t addr) {
    asm volatile("ldmatrix.sync.aligned.m8n8.x4.trans.shared.b16 {%0,%1,%2,%3}, [%4];"
                 : "=r"(r0), "=r"(r1), "=r"(r2), "=r"(r3) : "r"(addr));
}
__device__ __forceinline__ void mma_bf16(float* d, const uint32_t* a, uint32_t b0, uint32_t b1) {
    asm volatile(
        "mma.sync.aligned.m16n8k16.row.col.f32.bf16.bf16.f32 "
        "{%0,%1,%2,%3}, {%4,%5,%6,%7}, {%8,%9}, {%0,%1,%2,%3};"
        : "+f"(d[0]), "+f"(d[1]), "+f"(d[2]), "+f"(d[3])
        : "r"(a[0]), "r"(a[1]), "r"(a[2]), "r"(a[3]), "r"(b0), "r"(b1));
}

__global__ void __launch_bounds__(128, 4)
pointconv_mma(const float* __restrict__ x,
              const float* __restrict__ w,
              const float* __restrict__ bias,
              float* __restrict__ out)
{
    extern __shared__ char smem[];
    const uint32_t sbase = (uint32_t)__cvta_generic_to_shared(smem);
    const int tid  = threadIdx.x;
    const int wid  = tid >> 5;                  // 0..3
    const int lane = tid & 31;
    const int bid  = blockIdx.x;
    const int l    = bid >> 1;
    const int half = bid & 1;
    const int ph = l >> 5, pw = l & 31;
    const float* __restrict__ wl = w + (size_t)l * (NN * NN);

    // ---- patch gather -> bf16 hi/mid split -> fragment stream ----
    // fragbuf[s][nt][lane(bq*4+t)] = uint4{ bh0(k=2t,2t+1), bh1(k=2t+8,+9),
    //                                       bm0,            bm1 }
    {
        const int b  = tid & 31;
        const int cg = tid >> 5;               // 0..3
        const int nt = b >> 3, bq = b & 7;
        #pragma unroll
        for (int ci = 0; ci < 16; ci++) {
            const int c = cg * 16 + ci;
            #pragma unroll
            for (int kh = 0; kh < 2; kh++) {
                const float2 v = ldg_nc_v2(
                    x + (size_t)(((b * CC + c) * HH + 2 * ph + kh) * HH + 2 * pw));
                const int k  = c * 4 + kh * 2;            // even
                const int s  = k >> 4;
                const int kk = k & 15;
                const int t  = (kk >> 1) & 3;
                const int hi8 = (kk >= 8) ? 1 : 0;
                const uint32_t hp = cvt2(v.x, v.y);
                const uint32_t mp = cvt2(v.x - lo_f(hp), v.y - hi_f(hp));
                char* dst = smem + OFF_P + (s * 4 + nt) * 512 + (bq * 4 + t) * 16;
                *reinterpret_cast<uint32_t*>(dst + hi8 * 4)     = hp;
                *reinterpret_cast<uint32_t*>(dst + 8 + hi8 * 4) = mp;
            }
        }
    }

    float d[2][4][4];
    #pragma unroll
    for (int i = 0; i < 2; i++)
        #pragma unroll
        for (int j = 0; j < 4; j++)
            #pragma unroll
            for (int r = 0; r < 4; r++) d[i][j][r] = 0.0f;

    const int wbase = half * 128 + wid * 32;    // warp's p slice
    const int lm_m = lane >> 3, lm_r = lane & 7;

    // per-lane W addressing: 4 LDG.128 per stage cover 16 rows x 32 p
    const int lrow = lane >> 3;                 // 0..3
    const int lcol = (lane & 7) * 4;            // p offset within slice
    const float* __restrict__ wslice = wl + wbase + lcol;

    // ---- 2-stage LDG lookahead prologue ----
    float4 rw[2][4];
    #pragma unroll
    for (int j = 0; j < 4; j++)
        rw[0][j] = ldg_nc_v4(wslice + (size_t)(j * 4 + lrow) * NN);
    #pragma unroll
    for (int j = 0; j < 4; j++)
        rw[1][j] = ldg_nc_v4(wslice + (size_t)(KSTAGE + j * 4 + lrow) * NN);

    __syncthreads();                            // frag stream visible to all warps

    char* Aw = smem + OFF_A + wid * AWARP;      // hi at Aw, mid at Aw+2048
    const uint32_t Asm = sbase + OFF_A + wid * AWARP;
    const uint32_t sts_col = (uint32_t)((lane & 7) * 8);

    // ---- mainloop: warp-local, no __syncthreads ----
    #pragma unroll 1
    for (int s = 0; s < NSTG; s++) {
        const int cur = s & 1;

        float4 v0 = rw[cur][0], v1 = rw[cur][1], v2 = rw[cur][2], v3 = rw[cur][3];
        if (s + 2 < NSTG) {
            #pragma unroll
            for (int j = 0; j < 4; j++)
                rw[cur][j] = ldg_nc_v4(wslice + (size_t)((s + 2) * KSTAGE + j * 4 + lrow) * NN);
        }

        // convert + STS into private A tile
        {
            const float4 vv[4] = {v0, v1, v2, v3};
            #pragma unroll
            for (int j = 0; j < 4; j++) {
                const uint32_t r = (uint32_t)(j * 4 + lrow);
                const float4 va = vv[j];
                const uint32_t h01 = cvt2(va.x, va.y), h23 = cvt2(va.z, va.w);
                const uint32_t m01 = cvt2(va.x - lo_f(h01), va.y - hi_f(h01));
                const uint32_t m23 = cvt2(va.z - lo_f(h23), va.w - hi_f(h23));
                const uint32_t a = aswz(r, sts_col);
                *reinterpret_cast<uint2*>(Aw + a)        = make_uint2(h01, h23);
                *reinterpret_cast<uint2*>(Aw + 2048 + a) = make_uint2(m01, m23);
            }
        }
        __syncwarp();

        // B fragments: 4 x LDS.128 from the pre-formatted stream
        uint4 bf[4];
        #pragma unroll
        for (int nt = 0; nt < 4; nt++)
            bf[nt] = *reinterpret_cast<const uint4*>(
                smem + OFF_P + (s * 4 + nt) * 512 + lane * 16);

        #pragma unroll
        for (int pt = 0; pt < 2; pt++) {
            const uint32_t r  = (uint32_t)(lm_r + (lm_m >> 1) * 8);
            const uint32_t cb = (uint32_t)(pt * 32 + (lm_m & 1) * 16);
            const uint32_t lmoff = aswz(r, cb);
            uint32_t ah[4], am[4];
            ldsm4t(ah[0], ah[1], ah[2], ah[3], Asm + lmoff);
            ldsm4t(am[0], am[1], am[2], am[3], Asm + 2048 + lmoff);
            #pragma unroll
            for (int nt = 0; nt < 4; nt++) {
                mma_bf16(d[pt][nt], ah, bf[nt].x, bf[nt].y);
                mma_bf16(d[pt][nt], ah, bf[nt].z, bf[nt].w);
                mma_bf16(d[pt][nt], am, bf[nt].x, bf[nt].y);
            }
        }
        __syncwarp();   // ldsm done before next stage's STS overwrites the tile
    }

    // ---- epilogue: bias + scatter ----
    #pragma unroll
    for (int pt = 0; pt < 2; pt++) {
        const int p0 = wbase + pt * 16 + (lane >> 2);
        const int p1 = p0 + 8;
        const float bv0 = bias[p0 * LL + l];
        const float bv1 = bias[p1 * LL + l];
        const int c0 = p0 >> 2, kh0 = (p0 >> 1) & 1, kw0 = p0 & 1;
        const int c1 = p1 >> 2, kh1 = (p1 >> 1) & 1, kw1 = p1 & 1;
        #pragma unroll
        for (int nt = 0; nt < 4; nt++) {
            const int b = nt * 8 + 2 * (lane & 3);
            const size_t o0 = (size_t)(((b * CC + c0) * HH + 2 * ph + kh0) * HH + 2 * pw + kw0);
            const size_t o1 = (size_t)(((b * CC + c1) * HH + 2 * ph + kh1) * HH + 2 * pw + kw1);
            const size_t bs = (size_t)CC * HH * HH;
            out[o0]      = d[pt][nt][0] + bv0;
            out[o0 + bs] = d[pt][nt][1] + bv0;
            out[o1]      = d[pt][nt][2] + bv1;
            out[o1 + bs] = d[pt][nt][3] + bv1;
        }
    }
}

extern "C" void kernel_launch(void* const* d_in, const int* in_sizes, int n_in,
                              void* d_out, int out_size)
{
    const float* x    = (const float*)d_in[0];
    const float* w    = (const float*)d_in[1];
    const float* bias = (const float*)d_in[2];
    float* out        = (float*)d_out;

    cudaFuncSetAttribute(pointconv_mma,
                         cudaFuncAttributeMaxDynamicSharedMemorySize, SMEM_TOTAL);
    pointconv_mma<<<2 * LL, 128, SMEM_TOTAL>>>(x, w, bias, out);
}

// round 14
// speedup vs baseline: 1.3077x; 1.3077x over previous
#include <cuda_runtime.h>
#include <cstdint>

// PointConv: B=32, C=64, H=W=64, KH=KW=2 -> L=1024, n=256.
// Per l: D[p, b] = sum_k W[l][k][p] * patch[b][k] + bias[p, l]
// fp32 via 3-term bf16 split on mma.sync.m16n8k16.
// R14: A (=W^T) fragments built DIRECTLY in registers from per-lane scalar
//      LDGs (no A smem, no STS/ldmatrix, no mainloop barriers). B patch kept
//      as the R13-verified pre-formatted fragment stream in smem.

#define HH 64
#define CC 64
#define NN 256
#define LL 1024

#define KSTAGE 16
#define NSTG   16

#define OFF_P 0                    // frag stream: 16 s x 4 nt x 512B = 32768
#define SMEM_TOTAL 32768

__device__ __forceinline__ uint32_t cvt2(float lo, float hi) {  // pack {lo=low16, hi=high16}
    uint32_t r;
    asm("cvt.rn.bf16x2.f32 %0, %1, %2;" : "=r"(r) : "f"(hi), "f"(lo));
    return r;
}
__device__ __forceinline__ float lo_f(uint32_t p) { return __uint_as_float(p << 16); }
__device__ __forceinline__ float hi_f(uint32_t p) { return __uint_as_float(p & 0xffff0000u); }

__device__ __forceinline__ void mma_bf16(float* d, const uint32_t* a, uint32_t b0, uint32_t b1) {
    asm volatile(
        "mma.sync.aligned.m16n8k16.row.col.f32.bf16.bf16.f32 "
        "{%0,%1,%2,%3}, {%4,%5,%6,%7}, {%8,%9}, {%0,%1,%2,%3};"
        : "+f"(d[0]), "+f"(d[1]), "+f"(d[2]), "+f"(d[3])
        : "r"(a[0]), "r"(a[1]), "r"(a[2]), "r"(a[3]), "r"(b0), "r"(b1));
}

__global__ void __launch_bounds__(256, 2)
pointconv_mma(const float* __restrict__ x,
              const float* __restrict__ w,
              const float* __restrict__ bias,
              float* __restrict__ out)
{
    extern __shared__ char smem[];
    const int tid  = threadIdx.x;
    const int wid  = tid >> 5;                  // 0..7
    const int lane = tid & 31;
    const int l    = blockIdx.x;
    const int ph = l >> 5, pw = l & 31;
    const float* __restrict__ wl = w + (size_t)l * (NN * NN);

    // ---- patch gather -> bf16 hi/mid split -> fragment stream (R13 layout) ----
    // fragbuf[s][nt][(bq*4+t)*16] = uint4{ bh(k=2t,2t+1), bh(k=2t+8,+9),
    //                                      bm(k=2t,2t+1), bm(k=2t+8,+9) }
    {
        const int b  = tid & 31;
        const int cg = tid >> 5;               // 0..7
        const int nt = b >> 3, bq = b & 7;
        #pragma unroll
        for (int ci = 0; ci < 8; ci++) {
            const int c = cg * 8 + ci;
            #pragma unroll
            for (int kh = 0; kh < 2; kh++) {
                const float2 v = *reinterpret_cast<const float2*>(
                    x + (size_t)(((b * CC + c) * HH + 2 * ph + kh) * HH + 2 * pw));
                const int k  = c * 4 + kh * 2;            // even
                const int s  = k >> 4;
                const int kk = k & 15;
                const int t  = (kk >> 1) & 3;
                const int hi8 = (kk >= 8) ? 1 : 0;
                const uint32_t hp = cvt2(v.x, v.y);
                const uint32_t mp = cvt2(v.x - lo_f(hp), v.y - hi_f(hp));
                char* dst = smem + OFF_P + (s * 4 + nt) * 512 + (bq * 4 + t) * 16;
                *reinterpret_cast<uint32_t*>(dst + hi8 * 4)     = hp;
                *reinterpret_cast<uint32_t*>(dst + 8 + hi8 * 4) = mp;
            }
        }
    }

    float d[2][4][4];
    #pragma unroll
    for (int i = 0; i < 2; i++)
        #pragma unroll
        for (int j = 0; j < 4; j++)
            #pragma unroll
            for (int r = 0; r < 4; r++) d[i][j][r] = 0.0f;

    const int wbase = wid * 32;                 // warp's p slice
    const int g = lane >> 2;                    // fragment row within ptile
    const int c = (lane & 3) * 2;               // fragment k within chunk

    // per-lane A base: wl[(k=c)*NN + (p = wbase + g)]; ptile 1 adds +16.
    const float* __restrict__ lbase = wl + (size_t)c * NN + wbase + g;

    // ---- prologue: stage 0 raw fragment elements ----
    // raw[pt][j]: j = {0:(c,p), 1:(c+1,p), 2:(c,p+8), 3:(c+1,p+8),
    //                  4:(c+8,p), 5:(c+9,p), 6:(c+8,p+8), 7:(c+9,p+8)}
    float raw[2][8];
    #pragma unroll
    for (int pt = 0; pt < 2; pt++) {
        const float* bp = lbase + pt * 16;
        raw[pt][0] = bp[0];
        raw[pt][1] = bp[NN];
        raw[pt][2] = bp[8];
        raw[pt][3] = bp[NN + 8];
        raw[pt][4] = bp[8 * NN];
        raw[pt][5] = bp[9 * NN];
        raw[pt][6] = bp[8 * NN + 8];
        raw[pt][7] = bp[9 * NN + 8];
    }

    __syncthreads();                            // frag stream visible

    // ---- mainloop: barrier-free, register-direct A fragments ----
    #pragma unroll 1
    for (int s = 0; s < NSTG; s++) {
        // convert current raw -> A fragments (hi + mid)
        uint32_t ah[2][4], am[2][4];
        #pragma unroll
        for (int pt = 0; pt < 2; pt++) {
            #pragma unroll
            for (int j = 0; j < 4; j++) {
                const float v0 = raw[pt][j * 2];
                const float v1 = raw[pt][j * 2 + 1];
                const uint32_t h = cvt2(v0, v1);
                ah[pt][j] = h;
                am[pt][j] = cvt2(v0 - lo_f(h), v1 - hi_f(h));
            }
        }

        // issue next stage's raw loads (in flight during MMAs)
        if (s + 1 < NSTG) {
            const float* sb = lbase + (size_t)(s + 1) * KSTAGE * NN;
            #pragma unroll
            for (int pt = 0; pt < 2; pt++) {
                const float* bp = sb + pt * 16;
                raw[pt][0] = bp[0];
                raw[pt][1] = bp[NN];
                raw[pt][2] = bp[8];
                raw[pt][3] = bp[NN + 8];
                raw[pt][4] = bp[8 * NN];
                raw[pt][5] = bp[9 * NN];
                raw[pt][6] = bp[8 * NN + 8];
                raw[pt][7] = bp[9 * NN + 8];
            }
        }

        // B fragments: 4 x LDS.128 from the pre-formatted stream
        uint4 bf[4];
        #pragma unroll
        for (int nt = 0; nt < 4; nt++)
            bf[nt] = *reinterpret_cast<const uint4*>(
                smem + OFF_P + (s * 4 + nt) * 512 + lane * 16);

        #pragma unroll
        for (int pt = 0; pt < 2; pt++)
            #pragma unroll
            for (int nt = 0; nt < 4; nt++) {
                mma_bf16(d[pt][nt], ah[pt], bf[nt].x, bf[nt].y);   // hi * hi
                mma_bf16(d[pt][nt], ah[pt], bf[nt].z, bf[nt].w);   // hi * mid
                mma_bf16(d[pt][nt], am[pt], bf[nt].x, bf[nt].y);   // mid * hi
            }
    }

    // ---- epilogue: bias + scatter (R12-verified mapping) ----
    #pragma unroll
    for (int pt = 0; pt < 2; pt++) {
        const int p0 = wbase + pt * 16 + (lane >> 2);
        const int p1 = p0 + 8;
        const float bv0 = bias[p0 * LL + l];
        const float bv1 = bias[p1 * LL + l];
        const int c0 = p0 >> 2, kh0 = (p0 >> 1) & 1, kw0 = p0 & 1;
        const int c1 = p1 >> 2, kh1 = (p1 >> 1) & 1, kw1 = p1 & 1;
        #pragma unroll
        for (int nt = 0; nt < 4; nt++) {
            const int b = nt * 8 + 2 * (lane & 3);
            const size_t o0 = (size_t)(((b * CC + c0) * HH + 2 * ph + kh0) * HH + 2 * pw + kw0);
            const size_t o1 = (size_t)(((b * CC + c1) * HH + 2 * ph + kh1) * HH + 2 * pw + kw1);
            const size_t bs = (size_t)CC * HH * HH;
            out[o0]      = d[pt][nt][0] + bv0;
            out[o0 + bs] = d[pt][nt][1] + bv0;
            out[o1]      = d[pt][nt][2] + bv1;
            out[o1 + bs] = d[pt][nt][3] + bv1;
        }
    }
}

extern "C" void kernel_launch(void* const* d_in, const int* in_sizes, int n_in,
                              void* d_out, int out_size)
{
    const float* x    = (const float*)d_in[0];
    const float* w    = (const float*)d_in[1];
    const float* bias = (const float*)d_in[2];
    float* out        = (float*)d_out;

    cudaFuncSetAttribute(pointconv_mma,
                         cudaFuncAttributeMaxDynamicSharedMemorySize, SMEM_TOTAL);
    pointconv_mma<<<LL, 256, SMEM_TOTAL>>>(x, w, bias, out);
}